// round 1
// baseline (speedup 1.0000x reference)
#include <cuda_runtime.h>
#include <math.h>

#define Bn   4
#define Hn   256
#define Wn   320
#define HWn  (Hn*Wn)          // 81920
#define NPIX (Bn*HWn)         // 327680
#define CINn 65
#define NSn  256

// ---------------- scratch (device globals; no runtime alloc allowed) ---------
__device__ float g_z [NPIX*32];            // sigmoid(convz) output
__device__ float g_rh[NPIX*32];            // sigmoid(convr)*hidden
__device__ float g_t2[(size_t)64*NPIX];    // relu(dh2) output, layout [64][NPIX]

// ---------------- GRU conv: 3x3, 65->32, pad 1 -------------------------------
// MODE 0: z = sigmoid(conv(hx))            -> out = g_z
// MODE 1: rh = sigmoid(conv(hx))*hidden    -> out = g_rh
// MODE 2: q = tanh(conv([rh,x])); h=(1-z)h+zq -> out = h (in d_out)
template<int MODE>
__global__ void gru_conv(const float* __restrict__ pre,    // hidden (z,r) or g_rh (q)
                         const float* __restrict__ ndep,
                         const float* __restrict__ corr,
                         const float* __restrict__ wgt,    // [32][65][3][3]
                         const float* __restrict__ bias,   // [32]
                         const float* __restrict__ hidden,
                         const float* __restrict__ zbuf,
                         float* __restrict__ out)
{
    extern __shared__ float w_s[];   // [ic][j][oc] : 65*9*32 floats
    for (int i = threadIdx.x; i < CINn*9*32; i += blockDim.x) {
        int oc = i & 31; int rest = i >> 5;
        int j = rest % 9; int ic = rest / 9;
        w_s[i] = wgt[(oc*CINn + ic)*9 + j];
    }
    __syncthreads();

    int g = blockIdx.x * blockDim.x + threadIdx.x;   // grid exactly covers NPIX
    int b  = g / HWn;
    int hw = g - b*HWn;
    int y  = hw / Wn;
    int x  = hw - y*Wn;

    float acc[32];
    #pragma unroll
    for (int oc = 0; oc < 32; oc++) acc[oc] = bias[oc];

    bool yv0 = (y > 0), yv2 = (y < Hn-1);
    bool xv0 = (x > 0), xv2 = (x < Wn-1);

    for (int ic = 0; ic < CINn; ic++) {
        const float* src;
        if (ic < 32)       src = pre  + ((size_t)(b*32 + ic))*HWn;
        else if (ic == 32) src = ndep + (size_t)b*HWn;
        else               src = corr + ((size_t)(b*32 + (ic-33)))*HWn;

        float p[9];
        const float* r0 = src + (y-1)*Wn + x;
        const float* r1 = src +  y   *Wn + x;
        const float* r2 = src + (y+1)*Wn + x;
        p[0] = (yv0 && xv0) ? r0[-1] : 0.f;
        p[1] =  yv0         ? r0[ 0] : 0.f;
        p[2] = (yv0 && xv2) ? r0[ 1] : 0.f;
        p[3] =  xv0         ? r1[-1] : 0.f;
        p[4] =                r1[ 0];
        p[5] =  xv2         ? r1[ 1] : 0.f;
        p[6] = (yv2 && xv0) ? r2[-1] : 0.f;
        p[7] =  yv2         ? r2[ 0] : 0.f;
        p[8] = (yv2 && xv2) ? r2[ 1] : 0.f;

        const float* wrow = w_s + ic*9*32;
        #pragma unroll
        for (int j = 0; j < 9; j++) {
            #pragma unroll
            for (int oc4 = 0; oc4 < 8; oc4++) {
                float4 wv = *reinterpret_cast<const float4*>(wrow + j*32 + oc4*4);
                acc[oc4*4+0] = fmaf(p[j], wv.x, acc[oc4*4+0]);
                acc[oc4*4+1] = fmaf(p[j], wv.y, acc[oc4*4+1]);
                acc[oc4*4+2] = fmaf(p[j], wv.z, acc[oc4*4+2]);
                acc[oc4*4+3] = fmaf(p[j], wv.w, acc[oc4*4+3]);
            }
        }
    }

    #pragma unroll
    for (int oc = 0; oc < 32; oc++) {
        size_t oidx = ((size_t)(b*32 + oc))*HWn + hw;
        if (MODE == 0) {
            out[oidx] = 1.f / (1.f + __expf(-acc[oc]));
        } else if (MODE == 1) {
            float r = 1.f / (1.f + __expf(-acc[oc]));
            out[oidx] = r * hidden[oidx];
        } else {
            float q = tanhf(acc[oc]);
            float z = zbuf[oidx];
            out[oidx] = (1.f - z) * hidden[oidx] + z * q;
        }
    }
}

// ---------------- heads part 1: dual dilated 3x3 + conf head + dh2 -----------
__global__ void heads1(const float* __restrict__ h,
                       const float* __restrict__ dh1_w,   // [32][32][3][3]
                       const float* __restrict__ ch1_w,   // [32][32][3][3]
                       const float* __restrict__ dh2_w,   // [64][32]
                       const float* __restrict__ ch2_w,   // [32]
                       const float* __restrict__ ch2_b,   // [1]
                       float* __restrict__ t2g,           // [64][NPIX]
                       float* __restrict__ conf,
                       float* __restrict__ conf0)
{
    extern __shared__ float smem[];
    float* w1_s = smem;                  // 32*9*32
    float* c1_s = w1_s + 32*9*32;        // 32*9*32
    float* w2_s = c1_s + 32*9*32;        // [ic][64]
    for (int i = threadIdx.x; i < 32*9*32; i += blockDim.x) {
        int oc = i & 31; int rest = i >> 5;
        int j = rest % 9; int ic = rest / 9;
        w1_s[i] = dh1_w[(oc*32 + ic)*9 + j];
        c1_s[i] = ch1_w[(oc*32 + ic)*9 + j];
    }
    for (int i = threadIdx.x; i < 32*64; i += blockDim.x) {
        int oc = i & 63; int ic = i >> 6;
        w2_s[i] = dh2_w[oc*32 + ic];
    }
    __syncthreads();

    int g = blockIdx.x * blockDim.x + threadIdx.x;
    int b  = g / HWn;
    int hw = g - b*HWn;
    int y  = hw / Wn;
    int x  = hw - y*Wn;

    float a1[32], a2[32];
    #pragma unroll
    for (int i = 0; i < 32; i++) { a1[i] = 0.f; a2[i] = 0.f; }

    bool yv0 = (y >= 2), yv2 = (y <= Hn-3);
    bool xv0 = (x >= 2), xv2 = (x <= Wn-3);

    for (int ic = 0; ic < 32; ic++) {
        const float* src = h + ((size_t)(b*32 + ic))*HWn;
        float p[9];
        const float* r0 = src + (y-2)*Wn + x;
        const float* r1 = src +  y   *Wn + x;
        const float* r2 = src + (y+2)*Wn + x;
        p[0] = (yv0 && xv0) ? r0[-2] : 0.f;
        p[1] =  yv0         ? r0[ 0] : 0.f;
        p[2] = (yv0 && xv2) ? r0[ 2] : 0.f;
        p[3] =  xv0         ? r1[-2] : 0.f;
        p[4] =                r1[ 0];
        p[5] =  xv2         ? r1[ 2] : 0.f;
        p[6] = (yv2 && xv0) ? r2[-2] : 0.f;
        p[7] =  yv2         ? r2[ 0] : 0.f;
        p[8] = (yv2 && xv2) ? r2[ 2] : 0.f;

        const float* wr1 = w1_s + ic*9*32;
        const float* wr2 = c1_s + ic*9*32;
        #pragma unroll
        for (int j = 0; j < 9; j++) {
            #pragma unroll
            for (int oc4 = 0; oc4 < 8; oc4++) {
                float4 wa = *reinterpret_cast<const float4*>(wr1 + j*32 + oc4*4);
                float4 wb = *reinterpret_cast<const float4*>(wr2 + j*32 + oc4*4);
                a1[oc4*4+0] = fmaf(p[j], wa.x, a1[oc4*4+0]);
                a1[oc4*4+1] = fmaf(p[j], wa.y, a1[oc4*4+1]);
                a1[oc4*4+2] = fmaf(p[j], wa.z, a1[oc4*4+2]);
                a1[oc4*4+3] = fmaf(p[j], wa.w, a1[oc4*4+3]);
                a2[oc4*4+0] = fmaf(p[j], wb.x, a2[oc4*4+0]);
                a2[oc4*4+1] = fmaf(p[j], wb.y, a2[oc4*4+1]);
                a2[oc4*4+2] = fmaf(p[j], wb.z, a2[oc4*4+2]);
                a2[oc4*4+3] = fmaf(p[j], wb.w, a2[oc4*4+3]);
            }
        }
    }

    // confidence head: 1x1 over relu(a2)
    float cs = ch2_b[0];
    #pragma unroll
    for (int i = 0; i < 32; i++) {
        a1[i] = fmaxf(a1[i], 0.f);
        float c = fmaxf(a2[i], 0.f);
        cs = fmaf(c, ch2_w[i], cs);
    }
    conf0[g] = cs;
    conf[g]  = 1.f / (1.f + __expf(-cs));

    // dh2: 1x1, 32->64, relu
    float t2[64];
    #pragma unroll
    for (int i = 0; i < 64; i++) t2[i] = 0.f;
    #pragma unroll
    for (int ic = 0; ic < 32; ic++) {
        float v = a1[ic];
        #pragma unroll
        for (int oc4 = 0; oc4 < 16; oc4++) {
            float4 wv = *reinterpret_cast<const float4*>(w2_s + ic*64 + oc4*4);
            t2[oc4*4+0] = fmaf(v, wv.x, t2[oc4*4+0]);
            t2[oc4*4+1] = fmaf(v, wv.y, t2[oc4*4+1]);
            t2[oc4*4+2] = fmaf(v, wv.z, t2[oc4*4+2]);
            t2[oc4*4+3] = fmaf(v, wv.w, t2[oc4*4+3]);
        }
    }
    #pragma unroll
    for (int oc = 0; oc < 64; oc++)
        t2g[(size_t)oc*NPIX + g] = fmaxf(t2[oc], 0.f);
}

// ---------------- logits (64->256) + softmax + windowed depth regression -----
// Block: 256 threads = 8 warps, tile = 32 consecutive pixels.
// Thread (warp w, lane l): pixel g0+l, output channels [w*32, w*32+32).
__global__ void softmax_head(const float* __restrict__ t2g,  // [64][NPIX]
                             const float* __restrict__ w3,   // [256][64]
                             const float* __restrict__ b3,   // [256]
                             float* __restrict__ prob,
                             float* __restrict__ nd)
{
    extern __shared__ float smem[];
    float* w3_s = smem;                   // 256*64
    float* t2_s = w3_s + 256*64;          // [32][65] padded
    float* b3_s = t2_s + 32*65;           // 256
    float* redA = b3_s + 256;             // [8][33]
    float* redB = redA + 8*33;            // [8][33]
    int*   redI = (int*)(redB + 8*33);    // [8][33]

    int tid = threadIdx.x;
    for (int i = tid; i < 256*64/4; i += blockDim.x)
        reinterpret_cast<float4*>(w3_s)[i] = reinterpret_cast<const float4*>(w3)[i];
    if (tid < 256) b3_s[tid] = b3[tid];

    int g0 = blockIdx.x * 32;
    #pragma unroll
    for (int i = 0; i < 8; i++) {
        int idx = tid + i*256;
        int k = idx >> 5; int l = idx & 31;
        t2_s[l*65 + k] = t2g[(size_t)k*NPIX + g0 + l];
    }
    __syncthreads();

    int w = tid >> 5;
    int l = tid & 31;
    int g = g0 + l;
    int b  = g / HWn;
    int hw = g - b*HWn;

    const float* t2r = t2_s + l*65;
    float lg[32];
    float lmax = -3.4e38f; int lamax = 0;
    #pragma unroll
    for (int j = 0; j < 32; j++) {
        int oc = w*32 + j;
        float acc = b3_s[oc];
        const float* wrow = w3_s + oc*64;
        #pragma unroll
        for (int k4 = 0; k4 < 16; k4++) {
            float4 wv = *reinterpret_cast<const float4*>(wrow + k4*4);
            acc = fmaf(t2r[k4*4+0], wv.x, acc);
            acc = fmaf(t2r[k4*4+1], wv.y, acc);
            acc = fmaf(t2r[k4*4+2], wv.z, acc);
            acc = fmaf(t2r[k4*4+3], wv.w, acc);
        }
        lg[j] = acc;
        if (acc > lmax) { lmax = acc; lamax = oc; }
    }

    // cross-warp max + argmax (first occurrence: strict > with ascending warp)
    redA[w*33 + l] = lmax; redI[w*33 + l] = lamax;
    __syncthreads();
    float M = -3.4e38f; int A = 0;
    #pragma unroll
    for (int ww = 0; ww < 8; ww++) {
        float m = redA[ww*33 + l];
        if (m > M) { M = m; A = redI[ww*33 + l]; }
    }

    // sum of exp
    float s = 0.f;
    #pragma unroll
    for (int j = 0; j < 32; j++) { lg[j] = __expf(lg[j] - M); s += lg[j]; }
    __syncthreads();
    redA[w*33 + l] = s;
    __syncthreads();
    float S = 0.f;
    #pragma unroll
    for (int ww = 0; ww < 8; ww++) S += redA[ww*33 + l];
    float rS = 1.f / S;

    // windowed expectation around argmax with clamp multiplicity
    int lo = A - 4, hi = A + 4;
    int ocl = lo < 0 ? 0 : lo;
    int och = hi > 255 ? 255 : hi;
    float num = 0.f, den = 0.f;
    #pragma unroll
    for (int j = 0; j < 32; j++) {
        int oc = w*32 + j;
        if (oc >= ocl && oc <= och) {
            float mult = 1.f;
            if (oc == 0   && lo < 0)   mult += (float)(-lo);
            if (oc == 255 && hi > 255) mult += (float)(hi - 255);
            float pv = lg[j] * rS;
            num = fmaf(mult * (float)oc, pv, num);
            den = fmaf(mult, pv, den);
        }
    }
    __syncthreads();
    redA[w*33 + l] = num; redB[w*33 + l] = den;
    __syncthreads();
    if (w == 0) {
        float N = 0.f, D = 0.f;
        #pragma unroll
        for (int ww = 0; ww < 8; ww++) { N += redA[ww*33 + l]; D += redB[ww*33 + l]; }
        nd[g] = (N / (1e-6f + D)) * (1.0f / 255.0f);
    }

    // write probabilities (coalesced: lanes = consecutive hw)
    float* pbase = prob + (size_t)b*NSn*HWn + hw;
    #pragma unroll
    for (int j = 0; j < 32; j++)
        pbase[(size_t)(w*32 + j)*HWn] = lg[j] * rS;
}

// ---------------- launch ------------------------------------------------------
extern "C" void kernel_launch(void* const* d_in, const int* in_sizes, int n_in,
                              void* d_out, int out_size)
{
    const float* hidden  = (const float*)d_in[0];
    const float* ndep    = (const float*)d_in[1];
    const float* corr    = (const float*)d_in[2];
    const float* convz_w = (const float*)d_in[3];
    const float* convz_b = (const float*)d_in[4];
    const float* convr_w = (const float*)d_in[5];
    const float* convr_b = (const float*)d_in[6];
    const float* convq_w = (const float*)d_in[7];
    const float* convq_b = (const float*)d_in[8];
    const float* dh1_w   = (const float*)d_in[9];
    const float* dh2_w   = (const float*)d_in[10];
    const float* dh3_w   = (const float*)d_in[11];
    const float* dh3_b   = (const float*)d_in[12];
    const float* ch1_w   = (const float*)d_in[13];
    const float* ch2_w   = (const float*)d_in[14];
    const float* ch2_b   = (const float*)d_in[15];

    float* out   = (float*)d_out;
    float* out_h     = out;                              // [B,32,H,W]
    float* out_nd    = out_h  + (size_t)NPIX*32;         // [B,1,H,W]
    float* out_prob  = out_nd + NPIX;                    // [B,256,H,W]
    float* out_conf  = out_prob + (size_t)NPIX*256;      // [B,1,H,W]
    float* out_conf0 = out_conf + NPIX;                  // [B,1,H,W]

    float* zbuf;  cudaGetSymbolAddress((void**)&zbuf,  g_z);
    float* rhbuf; cudaGetSymbolAddress((void**)&rhbuf, g_rh);
    float* t2buf; cudaGetSymbolAddress((void**)&t2buf, g_t2);

    const int SMEM_GRU   = CINn*9*32*4;                       // 74880 B
    const int SMEM_HEAD1 = (32*9*32*2 + 32*64)*4;             // 81920 B
    const int SMEM_SMAX  = (256*64 + 32*65 + 256 + 3*8*33)*4; // 78048 B

    cudaFuncSetAttribute(gru_conv<0>,  cudaFuncAttributeMaxDynamicSharedMemorySize, SMEM_GRU);
    cudaFuncSetAttribute(gru_conv<1>,  cudaFuncAttributeMaxDynamicSharedMemorySize, SMEM_GRU);
    cudaFuncSetAttribute(gru_conv<2>,  cudaFuncAttributeMaxDynamicSharedMemorySize, SMEM_GRU);
    cudaFuncSetAttribute(heads1,       cudaFuncAttributeMaxDynamicSharedMemorySize, SMEM_HEAD1);
    cudaFuncSetAttribute(softmax_head, cudaFuncAttributeMaxDynamicSharedMemorySize, SMEM_SMAX);

    dim3 blk(256);
    dim3 grd(NPIX / 256);   // 1280, exact

    gru_conv<0><<<grd, blk, SMEM_GRU>>>(hidden, ndep, corr, convz_w, convz_b,
                                        hidden, nullptr, zbuf);
    gru_conv<1><<<grd, blk, SMEM_GRU>>>(hidden, ndep, corr, convr_w, convr_b,
                                        hidden, nullptr, rhbuf);
    gru_conv<2><<<grd, blk, SMEM_GRU>>>(rhbuf, ndep, corr, convq_w, convq_b,
                                        hidden, zbuf, out_h);
    heads1<<<grd, blk, SMEM_HEAD1>>>(out_h, dh1_w, ch1_w, dh2_w, ch2_w, ch2_b,
                                     t2buf, out_conf, out_conf0);
    softmax_head<<<NPIX / 32, 256, SMEM_SMAX>>>(t2buf, dh3_w, dh3_b,
                                                out_prob, out_nd);
}